// round 8
// baseline (speedup 1.0000x reference)
#include <cuda_runtime.h>

typedef unsigned long long u64;
typedef unsigned int u32;

#define B_TOT   256
#define IN_CAPS 1152
#define KDIM    8
#define NCAPS   10
#define DDIM    16
#define CHUNKS  36
#define I_PER   32
#define BGROUPS 8
#define SND     (B_TOT*NCAPS*DDIM)      /* 40960 */
#define FDIM    (IN_CAPS*KDIM)          /* 9216  */
#define XELEMS  (IN_CAPS*B_TOT*KDIM)    /* 2359296 */
#define XBLKS   ((XELEMS+1023)/1024)    /* 2304  */
#define WELEMS  (NCAPS*IN_CAPS*128)     /* 1474560 */
#define WBLKS   ((WELEMS+1023)/1024)    /* 1440  */
#define XSTRIDE (B_TOT*KDIM)            /* 2048 floats per i */

// ---------------- scratch (static device memory, no allocs) ----------------
__device__ float g_Wt[NCAPS*IN_CAPS*128];        // W transposed: [n][i][k][d]
__device__ float g_xI[XELEMS];                   // x re-laid:   [i][b][k]
__device__ float g_spart[CHUNKS*SND];            // per-chunk partial s
__device__ float g_vc[SND];                      // CUMULATIVE v  [b][n][d]

// ---------------- f32x2 helpers ----------------
__device__ __forceinline__ u64 pk2(float x, float y){
    u64 r; asm("mov.b64 %0,{%1,%2};" : "=l"(r) : "f"(x), "f"(y)); return r;
}
__device__ __forceinline__ void upk2(u64 a, float& x, float& y){
    asm("mov.b64 {%0,%1},%2;" : "=f"(x), "=f"(y) : "l"(a));
}
__device__ __forceinline__ u64 ffma2(u64 a, u64 b, u64 c){
    u64 d; asm("fma.rn.f32x2 %0,%1,%2,%3;" : "=l"(d) : "l"(a), "l"(b), "l"(c)); return d;
}
__device__ __forceinline__ u64 fmul2(u64 a, u64 b){
    u64 d; asm("mul.rn.f32x2 %0,%1,%2;" : "=l"(d) : "l"(a), "l"(b)); return d;
}
__device__ __forceinline__ u64 fadd2(u64 a, u64 b){
    u64 d; asm("add.rn.f32x2 %0,%1,%2;" : "=l"(d) : "l"(a), "l"(b)); return d;
}
__device__ __forceinline__ u32 smemu32(const void* p){
    u32 a; asm("{ .reg .u64 t; cvta.to.shared.u64 t, %1; cvt.u32.u64 %0, t; }" : "=r"(a) : "l"(p));
    return a;
}
__device__ __forceinline__ void cpasync16(u32 dst, const void* src){
    asm volatile("cp.async.ca.shared.global [%0],[%1],16;" :: "r"(dst), "l"(src));
}
__device__ __forceinline__ void cpcommit(){ asm volatile("cp.async.commit_group;"); }
__device__ __forceinline__ void cpwait1(){ asm volatile("cp.async.wait_group 1;"); }

// half-warp tu: this thread's d-half (hb = h*2) for TWO batches, sharing W loads.
// 16 LDS.128 (2-addr, conflict-free) + 64 FFMA2 per thread.
__device__ __forceinline__ void tu_half2(const ulonglong2* __restrict__ wr, int hb,
                                         const float* __restrict__ XL,
                                         const float* __restrict__ XH,
                                         u64* aL, u64* aH){
    #pragma unroll
    for (int k = 0; k < 8; k++){
        u64 xkL = pk2(XL[k], XL[k]);
        u64 xkH = pk2(XH[k], XH[k]);
        ulonglong2 w0 = wr[k*4 + hb];
        ulonglong2 w1 = wr[k*4 + hb + 1];
        if (k == 0){
            aL[0] = fmul2(w0.x, xkL); aL[1] = fmul2(w0.y, xkL);
            aL[2] = fmul2(w1.x, xkL); aL[3] = fmul2(w1.y, xkL);
            aH[0] = fmul2(w0.x, xkH); aH[1] = fmul2(w0.y, xkH);
            aH[2] = fmul2(w1.x, xkH); aH[3] = fmul2(w1.y, xkH);
        } else {
            aL[0] = ffma2(w0.x, xkL, aL[0]); aL[1] = ffma2(w0.y, xkL, aL[1]);
            aL[2] = ffma2(w1.x, xkL, aL[2]); aL[3] = ffma2(w1.y, xkL, aL[3]);
            aH[0] = ffma2(w0.x, xkH, aH[0]); aH[1] = ffma2(w0.y, xkH, aH[1]);
            aH[2] = ffma2(w1.x, xkH, aH[2]); aH[3] = ffma2(w1.y, xkH, aH[3]);
        }
    }
}

// ---------------- prep: both re-layouts in ONE kernel ----------------
// blocks [0,XBLKS): x [b][i][k] -> xI [i][b][k];  blocks [XBLKS,+WBLKS): W -> Wt
__global__ void k_prep(const float* __restrict__ x, const float* __restrict__ W){
    int xb = blockIdx.x;
    int tid = threadIdx.x;
    if (xb < XBLKS){
        int idx = xb * 1024 + tid;
        if (idx < XELEMS){
            int b = idx / FDIM;
            int f = idx - b * FDIM;
            g_xI[(f >> 3) * XSTRIDE + b * KDIM + (f & 7)] = x[idx];
        }
    } else {
        int idx = (xb - XBLKS) * 1024 + tid;
        if (idx < WELEMS){
            int k  = idx & 7;
            int d  = (idx >> 3) & 15;
            int ni = idx >> 7;
            g_Wt[(ni << 7) | (k << 4) | d] = W[idx];
        }
    }
}

// ---------------- main pass kernel ----------------
// warp = capsule n (10 warps). Half-warp d-split: lanes h=0 -> d[0:8), h=1 -> d[8:16).
// Each thread carries 2 batches (b=l16, b=l16+16). grid = (36 chunks, 8 bgroups), 2 CTAs/SM.
// ROUTE=0: c uniform -> pure accumulation, zero barriers.
// ROUTE=1: logit = tu . vc (cumulative v), 2 i-steps per barrier pair, reducer warps.
template<int ROUTE>
__global__ void __launch_bounds__(320, 2) k_pass(){
    __shared__ __align__(16) float ws[2][NCAPS*128];   // W slots: even-i / odd-i
    __shared__ float ex[4][NCAPS][32];                 // 4-way ping-pong exp exchange
    __shared__ float zi[4][32];                        // 1/Z per batch, per buffer

    const int tid   = threadIdx.x;
    const int n     = tid >> 5;
    const int lane  = tid & 31;
    const int l16   = lane & 15;
    const int h     = lane >> 4;
    const int hb    = h * 2;
    const int chunk = blockIdx.x;
    const int bg    = blockIdx.y;
    const int i0    = chunk * I_PER;
    const int b_lo  = bg * 32 + l16;
    const int b_hi  = b_lo + 16;

    u64 vL[4], vH[4];
    if (ROUTE){
        const u64* p0 = (const u64*)&g_vc[(b_lo*NCAPS + n)*DDIM + 8*h];
        const u64* p1 = (const u64*)&g_vc[(b_hi*NCAPS + n)*DDIM + 8*h];
        #pragma unroll
        for (int p = 0; p < 4; p++){ vL[p] = p0[p]; vH[p] = p1[p]; }
    }
    u64 sL[4], sH[4];
    #pragma unroll
    for (int p = 0; p < 4; p++){ sL[p] = 0ull; sH[p] = 0ull; }

    const float* wsrc = g_Wt + ((size_t)(n*IN_CAPS + i0))*128 + lane*4;
    const u32 wdst0 = smemu32(&ws[0][n*128 + lane*4]);
    const u32 wdst1 = smemu32(&ws[1][n*128 + lane*4]);
    const float* xl = g_xI + (size_t)i0 * XSTRIDE + b_lo * KDIM;
    const float* xh = g_xI + (size_t)i0 * XSTRIDE + b_hi * KDIM;

    if (!ROUTE){
        // -------- iteration 0: no routing, no barriers --------
        cpasync16(wdst0, wsrc); cpcommit();
        #pragma unroll 1
        for (int ii = 0; ii < I_PER; ii++){
            if (ii + 1 < I_PER) cpasync16((ii & 1) ? wdst0 : wdst1, wsrc + 128);
            cpcommit();
            wsrc += 128;
            cpwait1();
            float4 q0 = *(const float4*)xl, q1 = *(const float4*)(xl + 4);
            float4 r0 = *(const float4*)xh, r1 = *(const float4*)(xh + 4);
            xl += XSTRIDE; xh += XSTRIDE;
            float XL[8] = {q0.x,q0.y,q0.z,q0.w, q1.x,q1.y,q1.z,q1.w};
            float XH[8] = {r0.x,r0.y,r0.z,r0.w, r1.x,r1.y,r1.z,r1.w};
            u64 aL[4], aH[4];
            tu_half2((const ulonglong2*)&ws[ii & 1][n*128], hb, XL, XH, aL, aH);
            #pragma unroll
            for (int p = 0; p < 4; p++){ sL[p] = fadd2(sL[p], aL[p]); sH[p] = fadd2(sH[p], aH[p]); }
        }
    } else {
        // -------- routed iterations: 2 i-steps per barrier pair --------
        cpasync16(wdst0, wsrc);        cpcommit();   // W(i0+0)
        cpasync16(wdst1, wsrc + 128);  cpcommit();   // W(i0+1)
        #pragma unroll 1
        for (int ii = 0; ii < I_PER; ii += 2){
            const int bufA = ((ii >> 1) & 1) * 2;

            // ---- sub-step A (even i, slot0) ----
            cpwait1();                              // W(ii) ready
            float4 q0 = *(const float4*)xl, q1 = *(const float4*)(xl + 4);
            float4 r0 = *(const float4*)xh, r1 = *(const float4*)(xh + 4);
            float XAL[8] = {q0.x,q0.y,q0.z,q0.w, q1.x,q1.y,q1.z,q1.w};
            float XAH[8] = {r0.x,r0.y,r0.z,r0.w, r1.x,r1.y,r1.z,r1.w};
            u64 aAL[4], aAH[4];
            tu_half2((const ulonglong2*)&ws[0][n*128], hb, XAL, XAH, aAL, aAH);
            u64 dAL = fmul2(aAL[0], vL[0]);
            u64 dAH = fmul2(aAH[0], vH[0]);
            #pragma unroll
            for (int p = 1; p < 4; p++){ dAL = ffma2(aAL[p], vL[p], dAL); dAH = ffma2(aAH[p], vH[p], dAH); }
            float xlo, xhi, pAL, pAH;
            upk2(dAL, xlo, xhi); pAL = xlo + xhi;
            upk2(dAH, xlo, xhi); pAH = xlo + xhi;
            float fAL = pAL + __shfl_xor_sync(0xffffffffu, pAL, 16);   // combine d-halves
            float fAH = pAH + __shfl_xor_sync(0xffffffffu, pAH, 16);
            float eAL = __expf(fAL), eAH = __expf(fAH);   // |logit| small: no max-sub needed
            ex[bufA][n][lane] = h ? eAH : eAL;            // lane = l16+16h = own batch slot
            if (ii + 2 < I_PER) cpasync16(wdst0, wsrc + 256);   // W(ii+2)
            cpcommit();

            // ---- sub-step B (odd i, slot1) ----
            cpwait1();                              // W(ii+1) ready
            q0 = *(const float4*)(xl + XSTRIDE); q1 = *(const float4*)(xl + XSTRIDE + 4);
            r0 = *(const float4*)(xh + XSTRIDE); r1 = *(const float4*)(xh + XSTRIDE + 4);
            xl += 2 * XSTRIDE; xh += 2 * XSTRIDE;
            float XBL[8] = {q0.x,q0.y,q0.z,q0.w, q1.x,q1.y,q1.z,q1.w};
            float XBH[8] = {r0.x,r0.y,r0.z,r0.w, r1.x,r1.y,r1.z,r1.w};
            u64 aBL[4], aBH[4];
            tu_half2((const ulonglong2*)&ws[1][n*128], hb, XBL, XBH, aBL, aBH);
            u64 dBL = fmul2(aBL[0], vL[0]);
            u64 dBH = fmul2(aBH[0], vH[0]);
            #pragma unroll
            for (int p = 1; p < 4; p++){ dBL = ffma2(aBL[p], vL[p], dBL); dBH = ffma2(aBH[p], vH[p], dBH); }
            float pBL, pBH;
            upk2(dBL, xlo, xhi); pBL = xlo + xhi;
            upk2(dBH, xlo, xhi); pBH = xlo + xhi;
            float fBL = pBL + __shfl_xor_sync(0xffffffffu, pBL, 16);
            float fBH = pBH + __shfl_xor_sync(0xffffffffu, pBH, 16);
            float eBL = __expf(fBL), eBH = __expf(fBH);
            ex[bufA + 1][n][lane] = h ? eBH : eBL;
            if (ii + 3 < I_PER) cpasync16(wdst1, wsrc + 384);   // W(ii+3)
            cpcommit();
            wsrc += 256;

            __syncthreads();                        // all e's visible

            // reducer warps: warp0 -> A, warp1 -> B (one divide per lane)
            if (n < 2){
                const int buf = bufA + n;
                float Z = ex[buf][0][lane];
                #pragma unroll
                for (int j = 1; j < NCAPS; j++) Z += ex[buf][j][lane];
                zi[buf][lane] = __fdividef(1.0f, Z);
            }
            __syncthreads();                        // invZ visible

            float cAL = eAL * zi[bufA][l16];
            float cAH = eAH * zi[bufA][l16 + 16];
            float cBL = eBL * zi[bufA + 1][l16];
            float cBH = eBH * zi[bufA + 1][l16 + 16];
            u64 kAL = pk2(cAL, cAL), kAH = pk2(cAH, cAH);
            u64 kBL = pk2(cBL, cBL), kBH = pk2(cBH, cBH);
            #pragma unroll
            for (int p = 0; p < 4; p++){
                sL[p] = ffma2(aAL[p], kAL, sL[p]);
                sH[p] = ffma2(aAH[p], kAH, sH[p]);
                sL[p] = ffma2(aBL[p], kBL, sL[p]);
                sH[p] = ffma2(aBH[p], kBH, sH[p]);
            }
        }
    }

    // deterministic per-chunk partials (no atomics); thread owns d[8h:8h+8) of 2 batches
    float* spL = g_spart + ((size_t)(chunk*B_TOT + b_lo)*NCAPS + n)*DDIM + 8*h;
    float* spH = g_spart + ((size_t)(chunk*B_TOT + b_hi)*NCAPS + n)*DDIM + 8*h;
    ((ulonglong2*)spL)[0] = make_ulonglong2(sL[0], sL[1]);
    ((ulonglong2*)spL)[1] = make_ulonglong2(sL[2], sL[3]);
    ((ulonglong2*)spH)[0] = make_ulonglong2(sH[0], sH[1]);
    ((ulonglong2*)spH)[1] = make_ulonglong2(sH[2], sH[3]);
}

// ---------------- reduce partials + squash (2 warps per (b,n)) ----------------
// MODE 0: vc = v ; MODE 1: vc += v ; MODE 2: out = v
template<int MODE>
__global__ void k_reduce(float* __restrict__ out, float scale){
    __shared__ float red[4][2][16];
    const int tid  = threadIdx.x;
    const int wid  = tid >> 5;           // 0..7
    const int lane = tid & 31;
    const int pib  = wid >> 1;           // pair-in-block 0..3
    const int half = wid & 1;
    const int pair = blockIdx.x * 4 + pib;     // (b,n) in [0, 2560)
    const int d    = lane & 15;
    const int hh   = lane >> 4;
    const size_t base = (size_t)pair * DDIM + d;

    float s = 0.f;
    #pragma unroll
    for (int j = 0; j < 9; j++)
        s += g_spart[(size_t)(half*2 + hh + 4*j) * SND + base];
    s += __shfl_xor_sync(0xffffffffu, s, 16);
    if (lane < 16) red[pib][half][d] = s;
    __syncthreads();
    if (half == 0){
        float st = (red[pib][0][d] + red[pib][1][d]) * scale;
        float sq = st * st;
        sq += __shfl_xor_sync(0xffffffffu, sq, 1);
        sq += __shfl_xor_sync(0xffffffffu, sq, 2);
        sq += __shfl_xor_sync(0xffffffffu, sq, 4);
        sq += __shfl_xor_sync(0xffffffffu, sq, 8);
        float nrm = sqrtf(sq);
        float vv = (sq / (1.0f + sq)) * (st / (nrm + 1e-8f));
        if (lane < 16){
            if (MODE == 0)      g_vc[base] = vv;
            else if (MODE == 1) g_vc[base] += vv;
            else                out[base] = vv;
        }
    }
}

// ---------------- launch ----------------
extern "C" void kernel_launch(void* const* d_in, const int* in_sizes, int n_in,
                              void* d_out, int out_size){
    const float* x = (const float*)d_in[0];
    const float* W = (const float*)d_in[1];
    if (n_in >= 2 && in_sizes[0] == WELEMS){   // defensive order swap
        const float* t = x; x = W; W = t;
    }
    float* out = (float*)d_out;

    k_prep<<<XBLKS + WBLKS, 1024>>>(x, W);

    dim3 pg(CHUNKS, BGROUPS);
    const int RB = (B_TOT*NCAPS)/4;    // 640 blocks

    k_pass<0><<<pg, 320>>>();
    k_reduce<0><<<RB, 256>>>(nullptr, 0.1f);   // c = softmax(0) = 1/10

    k_pass<1><<<pg, 320>>>();
    k_reduce<1><<<RB, 256>>>(nullptr, 1.0f);

    k_pass<1><<<pg, 320>>>();
    k_reduce<1><<<RB, 256>>>(nullptr, 1.0f);

    k_pass<1><<<pg, 320>>>();
    k_reduce<2><<<RB, 256>>>(out, 1.0f);
}